// round 10
// baseline (speedup 1.0000x reference)
#include <cuda_runtime.h>

// GARCH(1,1): h[t] = (omega + alpha*r[t-1]^2) + beta*h[t-1], h[0] = var(r, ddof=1)
// out[0..n) = sqrt(h), out[n..2n) = h
//
// Proven-fastest main design (padded-smem staging + per-thread 32-chunk
// recurrence + Hillis-Steele exact block stitch), int indexing, with the
// t<256 fixup FUSED as a last-block ticket tail (separate 1-block kernels
// cost a fixed ~10us on this setup). Release fence executed by tid0 only
// (cumulative after __syncthreads).
// beta<1 => contractive (beta^256 ~ 8e-19 < fp32 ulp): tiles carry a 256-elem
// warm-up halo; intra-block stitch is exact. True h[t] = h_hat[t] + beta^t*h0
// (linearity): the h0 term only matters for t < ~100 and is patched by the
// last block, which also reduces the fp32 variance partials.

#define TPB   256
#define CPT   32
#define TILE  (TPB*CPT)        // 8192
#define HALO  256              // == TPB: phase-5 halo skip is exactly it==0
#define OPB   (TILE - HALO)    // 7936
#define FIXN  256
#define MAXB  4096

__device__ double   g_psum[MAXB];
__device__ double   g_psumsq[MAXB];
__device__ unsigned g_ticket = 0;

__device__ __forceinline__ int padidx(int k) { return k + (k >> 5); }

__device__ __forceinline__ float fsqrt_ap(float x) {
    float y; asm("sqrt.approx.f32 %0, %1;" : "=f"(y) : "f"(x)); return y;
}

__global__ void __launch_bounds__(TPB)
garch_fused(const float* __restrict__ r,
            const float* __restrict__ omega_p,
            const float* __restrict__ alpha_p,
            const float* __restrict__ beta_p,
            float* __restrict__ out,
            int n, int nblocks, int write_h)
{
    __shared__ __align__(16) float bpad[TILE + TILE/32];
    __shared__ float    sscan[TPB];
    __shared__ double   wsum[TPB/32], wsq[TPB/32];
    __shared__ unsigned s_ticket;
    __shared__ float    sh0;

    const int   tid   = threadIdx.x;
    const float omega = *omega_p;
    const float alpha = *alpha_p;
    const float beta  = *beta_p;

    // int indexing: n <= 2^24, all t / n+t fit comfortably in int32
    const int tile_t0 = blockIdx.x * OPB + 1 - HALO;
    const int s0      = tile_t0 - 1;                     // r index for k=0

    float vs = 0.0f, vq = 0.0f;                          // fp32 variance partials

    // ---- Phase 1: load r, compute drivers b[t] = omega + alpha*r[t-1]^2 ----
    const bool interior = (s0 >= 0) && (s0 + TILE < n);
    if (interior) {
        const float4* __restrict__ r4 = (const float4*)(r + s0);   // 16B aligned
        #pragma unroll
        for (int it = 0; it < TILE / (4 * TPB); ++it) {
            int q = tid + it * TPB;
            float4 v = r4[q];
            int k = 4 * q;
            int base = padidx(k);                        // k%4==0: no pad break
            bpad[base + 0] = fmaf(alpha * v.x, v.x, omega);
            bpad[base + 1] = fmaf(alpha * v.y, v.y, omega);
            bpad[base + 2] = fmaf(alpha * v.z, v.z, omega);
            bpad[base + 3] = fmaf(alpha * v.w, v.w, omega);
            if (k >= HALO) {                             // exclusive region
                vs += (v.x + v.y) + (v.z + v.w);
                vq += fmaf(v.x, v.x, v.y * v.y) + fmaf(v.z, v.z, v.w * v.w);
            }
        }
    } else {
        #pragma unroll
        for (int it = 0; it < TILE / TPB; ++it) {
            int k = tid + it * TPB;
            int t = tile_t0 + k;
            float b = 0.0f;
            if (t >= 1 && t < n) {
                float rv = r[t - 1];
                b = fmaf(alpha * rv, rv, omega);
                if (k >= HALO) { vs += rv; vq = fmaf(rv, rv, vq); }
            }
            bpad[padidx(k)] = b;
        }
    }
    if (blockIdx.x == 0 && tid == 0) {                   // r[n-1]: never a driver
        float rv = r[n - 1];
        vs += rv; vq = fmaf(rv, rv, vq);
    }
    __syncthreads();

    // ---- Phase 2: per-thread serial recurrence from zero state ----
    float p[CPT];
    {
        float h = 0.0f;
        const int base = padidx(tid * CPT);              // tid*33: conflict-free
        #pragma unroll
        for (int j = 0; j < CPT; ++j) {
            h = fmaf(beta, h, bpad[base + j]);
            p[j] = h;
        }
        sscan[tid] = h;
    }
    __syncthreads();

    // ---- Phase 3: exact stitch S_i = E_i + beta^32 * S_{i-1} ----
    {
        float b2 = beta * beta, b4 = b2 * b2, b8 = b4 * b4, b16 = b8 * b8;
        float m = b16 * b16;                             // beta^32
        for (int d = 1; d < TPB; d <<= 1) {
            float v  = sscan[tid];
            float lo = (tid >= d) ? sscan[tid - d] : 0.0f;
            __syncthreads();
            sscan[tid] = fmaf(m, lo, v);
            m *= m;
            __syncthreads();
        }
    }
    float carry = (tid >= 1) ? sscan[tid - 1] : 0.0f;

    // ---- Phase 4: apply carry, stage h in shared ----
    {
        const int base = padidx(tid * CPT);
        float bp = beta;
        #pragma unroll
        for (int j = 0; j < CPT; ++j) {
            float h = fmaf(bp, carry, p[j]);
            bpad[base + j] = h;
            bp *= beta;
        }
    }
    __syncthreads();

    // ---- Phase 5: coalesced stores of sqrt(h) and h ----
    // k = tid + it*TPB; HALO==TPB so it==0 is pure halo: start at it=1.
    if (tile_t0 + TILE <= n) {                           // interior output tile
        if (write_h) {
            #pragma unroll
            for (int it = 1; it < TILE / TPB; ++it) {
                int k = tid + it * TPB;
                int t = tile_t0 + k;
                float h = bpad[padidx(k)];
                out[t]     = fsqrt_ap(h);
                out[n + t] = h;
            }
        } else {
            #pragma unroll
            for (int it = 1; it < TILE / TPB; ++it) {
                int k = tid + it * TPB;
                float h = bpad[padidx(k)];
                out[tile_t0 + k] = fsqrt_ap(h);
            }
        }
    } else {                                             // right-edge tile
        #pragma unroll
        for (int it = 1; it < TILE / TPB; ++it) {
            int k = tid + it * TPB;
            int t = tile_t0 + k;
            if (t < n) {
                float h = bpad[padidx(k)];
                out[t] = fsqrt_ap(h);
                if (write_h) out[n + t] = h;
            }
        }
    }

    // ---- Phase 6: deterministic variance reduce ----
    const int wid = tid >> 5, lane = tid & 31;
    const unsigned FULL = 0xFFFFFFFFu;
    #pragma unroll
    for (int off = 16; off; off >>= 1) {
        vs += __shfl_down_sync(FULL, vs, off);
        vq += __shfl_down_sync(FULL, vq, off);
    }
    if (lane == 0) { wsum[wid] = (double)vs; wsq[wid] = (double)vq; }
    __syncthreads();
    if (tid == 0) {
        double a = 0.0, b_ = 0.0;
        #pragma unroll
        for (int w = 0; w < TPB / 32; ++w) { a += wsum[w]; b_ += wsq[w]; }
        g_psum[blockIdx.x]   = a;
        g_psumsq[blockIdx.x] = b_;
        // release: after the barrier above, tid0's fence covers the whole
        // block's prior stores (fence cumulativity)
        __threadfence();
        s_ticket = atomicAdd(&g_ticket, 1u);
    }
    __syncthreads();
    if (s_ticket != (unsigned)(nblocks - 1)) return;

    // ================= last block: fused fixup =================
    if (tid == 0) { g_ticket = 0; __threadfence(); }     // reset + acquire
    __syncthreads();

    const int lim = (FIXN < n) ? FIXN : n;
    float hhat = 0.0f;
    if (write_h && tid < lim) hhat = out[n + tid];       // h_hat[t] prefetch

    double* red  = (double*)bpad;                        // reuse staging buffer
    double* red2 = red + TPB;
    {
        double a0 = 0.0, a1 = 0.0, q0 = 0.0, q1 = 0.0;
        int i = tid;
        for (; i + TPB < nblocks; i += 2 * TPB) {
            a0 += g_psum[i];        q0 += g_psumsq[i];
            a1 += g_psum[i + TPB];  q1 += g_psumsq[i + TPB];
        }
        for (; i < nblocks; i += TPB) { a0 += g_psum[i]; q0 += g_psumsq[i]; }
        red[tid]  = a0 + a1;
        red2[tid] = q0 + q1;
    }
    __syncthreads();
    for (int s = TPB / 2; s; s >>= 1) {
        if (tid < s) { red[tid] += red[tid + s]; red2[tid] += red2[tid + s]; }
        __syncthreads();
    }
    if (tid == 0) {
        double S = red[0], Q = red2[0];
        sh0 = (float)((Q - S * S / (double)n) / (double)(n - 1));
    }
    __syncthreads();

    const float h0 = sh0;
    if (write_h) {
        // h[t] = h_hat[t] + beta^t * h0 (linearity); lim <= TPB: one pass
        if (tid < lim) {
            float bp = 1.0f, bb = beta; int e = tid;
            while (e) { if (e & 1) bp *= bb; bb *= bb; e >>= 1; }
            float hh = (tid == 0) ? h0 : fmaf(bp, h0, hhat);
            out[n + tid] = hh;
            out[tid] = fsqrt_ap(hh);
        }
    } else {
        if (tid == 0) {                                  // rare fallback
            float h = h0;
            out[0] = fsqrt_ap(h);
            for (int t = 1; t < lim; ++t) {
                float rv = r[t - 1];
                h = fmaf(beta, h, fmaf(alpha * rv, rv, omega));
                out[t] = fsqrt_ap(h);
            }
        }
    }
}

extern "C" void kernel_launch(void* const* d_in, const int* in_sizes, int n_in,
                              void* d_out, int out_size)
{
    const float* r  = (const float*)d_in[0];
    const float* om = (const float*)d_in[1];
    const float* al = (const float*)d_in[2];
    const float* be = (const float*)d_in[3];
    float* out = (float*)d_out;

    const int n = in_sizes[0];
    const int write_h = (out_size >= 2 * n) ? 1 : 0;

    int nblocks = (n - 1 + OPB - 1) / OPB;
    if (nblocks < 1)    nblocks = 1;
    if (nblocks > MAXB) nblocks = MAXB;

    garch_fused<<<nblocks, TPB>>>(r, om, al, be, out, n, nblocks, write_h);
}

// round 11
// speedup vs baseline: 1.0493x; 1.0493x over previous
#include <cuda_runtime.h>

// GARCH(1,1): h[t] = (omega + alpha*r[t-1]^2) + beta*h[t-1], h[0] = var(r, ddof=1)
// out[0..n) = sqrt(h), out[n..2n) = h
//
// Measured-fastest main design (R8: padded-smem staging, per-thread 32-chunk
// recurrence, Hillis-Steele exact block stitch) kept byte-for-byte, with the
// t<256 fixup fused as a minimal last-block ticket tail, and a hard register
// ceiling (__launch_bounds__(256,5) -> 48 regs) so the tail cannot deflate
// main-loop occupancy (rounds 9/10 showed regs 64/80 -> occ 46/35% -> slow).
// beta<1 => contractive (beta^256 ~ 8e-19 < fp32 ulp): tiles carry a 256-elem
// warm-up halo; intra-block stitch is exact. True h[t] = h_hat[t] + beta^t*h0
// (linearity): the h0 term only matters for t < ~100, patched by the last
// block, which also reduces the fp32 variance partials.

#define TPB   256
#define CPT   32
#define TILE  (TPB*CPT)        // 8192
#define HALO  256
#define OPB   (TILE - HALO)    // 7936
#define FIXN  256
#define MAXB  4096

__device__ double   g_psum[MAXB];
__device__ double   g_psumsq[MAXB];
__device__ unsigned g_ticket = 0;

__device__ __forceinline__ int padidx(int k) { return k + (k >> 5); }

__device__ __forceinline__ float fsqrt_ap(float x) {
    float y; asm("sqrt.approx.f32 %0, %1;" : "=f"(y) : "f"(x)); return y;
}

__global__ void __launch_bounds__(TPB, 5)
garch_fused(const float* __restrict__ r,
            const float* __restrict__ omega_p,
            const float* __restrict__ alpha_p,
            const float* __restrict__ beta_p,
            float* __restrict__ out,
            int n, int nblocks, int write_h)
{
    __shared__ float    bpad[TILE + TILE/32];
    __shared__ float    sscan[TPB];
    __shared__ double   wsum[TPB/32], wsq[TPB/32];
    __shared__ unsigned s_ticket;
    __shared__ float    sh0;

    const int   tid   = threadIdx.x;
    const float omega = *omega_p;
    const float alpha = *alpha_p;
    const float beta  = *beta_p;

    const long long tile_t0 = (long long)blockIdx.x * OPB + 1 - HALO;
    const long long s0      = tile_t0 - 1;              // r index for k=0

    float vs = 0.0f, vq = 0.0f;                          // fp32 variance partials

    // ---- Phase 1: load r, compute drivers b[t] = omega + alpha*r[t-1]^2 ----
    const bool interior = (s0 >= 0) && (s0 + TILE < (long long)n);
    if (interior) {
        const float4* __restrict__ r4 = (const float4*)(r + s0);   // 16B aligned
        #pragma unroll
        for (int it = 0; it < TILE / (4 * TPB); ++it) {
            int q = tid + it * TPB;
            float4 v = r4[q];
            int k = 4 * q;
            int base = padidx(k);                        // k%4==0: no pad break
            bpad[base + 0] = fmaf(alpha * v.x, v.x, omega);
            bpad[base + 1] = fmaf(alpha * v.y, v.y, omega);
            bpad[base + 2] = fmaf(alpha * v.z, v.z, omega);
            bpad[base + 3] = fmaf(alpha * v.w, v.w, omega);
            if (k >= HALO) {                             // exclusive region
                vs += (v.x + v.y) + (v.z + v.w);
                vq += fmaf(v.x, v.x, v.y * v.y) + fmaf(v.z, v.z, v.w * v.w);
            }
        }
    } else {
        #pragma unroll
        for (int it = 0; it < TILE / TPB; ++it) {
            int k = tid + it * TPB;
            long long t = tile_t0 + k;
            float b = 0.0f;
            if (t >= 1 && t < (long long)n) {
                float rv = r[t - 1];
                b = fmaf(alpha * rv, rv, omega);
                if (k >= HALO) { vs += rv; vq = fmaf(rv, rv, vq); }
            }
            bpad[padidx(k)] = b;
        }
    }
    if (blockIdx.x == 0 && tid == 0) {                   // r[n-1]: never a driver
        float rv = r[n - 1];
        vs += rv; vq = fmaf(rv, rv, vq);
    }
    __syncthreads();

    // ---- Phase 2: per-thread serial recurrence from zero state ----
    float p[CPT];
    {
        float h = 0.0f;
        const int base = padidx(tid * CPT);              // tid*33: conflict-free
        #pragma unroll
        for (int j = 0; j < CPT; ++j) {
            h = fmaf(beta, h, bpad[base + j]);
            p[j] = h;
        }
        sscan[tid] = h;
    }
    __syncthreads();

    // ---- Phase 3: exact stitch S_i = E_i + beta^32 * S_{i-1} ----
    {
        float b2 = beta * beta, b4 = b2 * b2, b8 = b4 * b4, b16 = b8 * b8;
        float m = b16 * b16;                             // beta^32
        for (int d = 1; d < TPB; d <<= 1) {
            float v  = sscan[tid];
            float lo = (tid >= d) ? sscan[tid - d] : 0.0f;
            __syncthreads();
            sscan[tid] = fmaf(m, lo, v);
            m *= m;
            __syncthreads();
        }
    }
    float carry = (tid >= 1) ? sscan[tid - 1] : 0.0f;

    // ---- Phase 4: apply carry, stage h in shared ----
    {
        const int base = padidx(tid * CPT);
        float bp = beta;
        #pragma unroll
        for (int j = 0; j < CPT; ++j) {
            float h = fmaf(bp, carry, p[j]);
            bpad[base + j] = h;
            bp *= beta;
        }
    }
    __syncthreads();

    // ---- Phase 5: coalesced stores of sqrt(h) and h ----
    #pragma unroll
    for (int it = 0; it < TILE / TPB; ++it) {
        int k = tid + it * TPB;
        if (k < HALO) continue;
        long long t = tile_t0 + k;
        if (t < (long long)n) {
            float h = bpad[padidx(k)];
            out[t] = fsqrt_ap(h);
            if (write_h) out[(long long)n + t] = h;
        }
    }

    // ---- Phase 6: deterministic variance reduce ----
    const int wid = tid >> 5, lane = tid & 31;
    const unsigned FULL = 0xFFFFFFFFu;
    #pragma unroll
    for (int off = 16; off; off >>= 1) {
        vs += __shfl_down_sync(FULL, vs, off);
        vq += __shfl_down_sync(FULL, vq, off);
    }
    if (lane == 0) { wsum[wid] = (double)vs; wsq[wid] = (double)vq; }
    __syncthreads();
    if (tid == 0) {
        double a = 0.0, b_ = 0.0;
        #pragma unroll
        for (int w = 0; w < TPB / 32; ++w) { a += wsum[w]; b_ += wsq[w]; }
        g_psum[blockIdx.x]   = a;
        g_psumsq[blockIdx.x] = b_;
        // release: after the barrier above, tid0's fence covers the whole
        // block's prior stores (fence cumulativity)
        __threadfence();
        s_ticket = atomicAdd(&g_ticket, 1u);
    }
    __syncthreads();
    if (s_ticket != (unsigned)(nblocks - 1)) return;

    // ================= last block: minimal fused fixup =================
    if (tid == 0) { g_ticket = 0; __threadfence(); }     // reset + acquire
    __syncthreads();

    const int lim = (FIXN < n) ? FIXN : n;
    float hhat = 0.0f;
    if (write_h && tid < lim) hhat = out[(long long)n + tid];

    double* red  = (double*)bpad;                        // reuse staging buffer
    double* red2 = red + TPB;
    {
        double a = 0.0, q = 0.0;
        for (int i = tid; i < nblocks; i += TPB) { a += g_psum[i]; q += g_psumsq[i]; }
        red[tid] = a; red2[tid] = q;
    }
    __syncthreads();
    for (int s = TPB / 2; s; s >>= 1) {
        if (tid < s) { red[tid] += red[tid + s]; red2[tid] += red2[tid + s]; }
        __syncthreads();
    }
    if (tid == 0) {
        double S = red[0], Q = red2[0];
        sh0 = (float)((Q - S * S / (double)n) / (double)(n - 1));
    }
    __syncthreads();

    const float h0 = sh0;
    if (write_h) {
        // h[t] = h_hat[t] + beta^t * h0 (linearity); lim <= TPB: one pass
        if (tid < lim) {
            float bp = 1.0f, bb = beta; int e = tid;
            while (e) { if (e & 1) bp *= bb; bb *= bb; e >>= 1; }
            float hh = (tid == 0) ? h0 : fmaf(bp, h0, hhat);
            out[(long long)n + tid] = hh;
            out[tid] = fsqrt_ap(hh);
        }
    } else {
        if (tid == 0) {                                  // rare fallback
            float h = h0;
            out[0] = fsqrt_ap(h);
            for (int t = 1; t < lim; ++t) {
                float rv = r[t - 1];
                h = fmaf(beta, h, fmaf(alpha * rv, rv, omega));
                out[t] = fsqrt_ap(h);
            }
        }
    }
}

extern "C" void kernel_launch(void* const* d_in, const int* in_sizes, int n_in,
                              void* d_out, int out_size)
{
    const float* r  = (const float*)d_in[0];
    const float* om = (const float*)d_in[1];
    const float* al = (const float*)d_in[2];
    const float* be = (const float*)d_in[3];
    float* out = (float*)d_out;

    const int n = in_sizes[0];
    const int write_h = (out_size >= 2 * n) ? 1 : 0;

    int nblocks = (n - 1 + OPB - 1) / OPB;
    if (nblocks < 1)    nblocks = 1;
    if (nblocks > MAXB) nblocks = MAXB;

    garch_fused<<<nblocks, TPB>>>(r, om, al, be, out, n, nblocks, write_h);
}